// round 10
// baseline (speedup 1.0000x reference)
#include <cuda_runtime.h>
#include <float.h>

#define NB 32
#define NS 512
#define NH 1024
#define NCAND 256
#define NL 34
#define NLP 36      // labels padded to 9 quads
#define NCH 16      // chunks per sequence
#define CSZ 32      // tokens per chunk
#define SPLIT 8     // K-split (warps per gemm block)
#define KS (2 * NH / SPLIT)   // 256 floats per split
#define CMB (NB * NCH * 2)    // 1024 chunk cells (2 h-halves)
#define WTB 288               // wt blocks (288*256 = 36*2048)

// Scratch (__device__ globals; no allocation allowed)
__device__ float g_cmax[NB * NCH * NH];
__device__ float g_plp[NCAND * NH];
__device__ float g_prp[NCAND * NH];
__device__ float g_pooled[NCAND * 2 * NH];
__device__ float g_Wt[NLP * 2 * NH];             // W transposed+padded [36][2048]

__device__ __forceinline__ float2 f2max(float2 a, float2 b) {
    float2 r;
    r.x = fmaxf(a.x, b.x);
    r.y = fmaxf(a.y, b.y);
    return r;
}

// ---------------------------------------------------------------------------
// Kernel A (fused): per-(b,q,h-half) chunk maxes. Thread owns 2 h via float2,
// running max over 32 tokens with bounded unroll (8 loads in flight -> ~35
// regs, high occupancy; round-9's full unroll hit 152 regs / 12% occ).
// Candidate in-chunk partials re-read the 64 KB block tile from L1.
// W transpose rides along as trailing blocks. hidden DRAM traffic: 64 MB.
// ---------------------------------------------------------------------------
__global__ __launch_bounds__(256) void k_A(const float* __restrict__ hidden,
                                           const float* __restrict__ W,
                                           const int* __restrict__ cb,
                                           const int* __restrict__ cc) {
    int bid = blockIdx.x;
    int tid = threadIdx.x;

    if (bid >= CMB) {   // ---- W transpose part ----
        int idx = (bid - CMB) * 256 + tid;
        int l = idx >> 11;
        int k = idx & (2 * NH - 1);
        g_Wt[idx] = (l < NL) ? W[(size_t)k * NL + l] : 0.f;
        return;
    }

    // ---- chunk cell: bid = b*32 + q*2 + hb; thread owns 2 h ----
    __shared__ int s_cnt;
    __shared__ int s_n[NCAND];
    __shared__ int s_r[NCAND];

    int b = bid >> 5;
    int rest = bid & 31;
    int q = rest >> 1;
    int hb = rest & 1;
    int h2 = hb * 256 + tid;        // float2 index within row

    if (tid == 0) s_cnt = 0;
    __syncthreads();
    {
        int cn = cc[tid];           // tid in [0,256) == NCAND
        if (cb[tid] == b && (cn >> 5) == q) {
            int p = atomicAdd(&s_cnt, 1);
            s_n[p] = tid;
            s_r[p] = cn & 31;
        }
    }

    const float2* base =
        (const float2*)(hidden + ((size_t)(b * NS + q * CSZ)) * NH) + h2;
    const int rs2 = NH / 2;         // token stride in float2

    float2 m = make_float2(-FLT_MAX, -FLT_MAX);
#pragma unroll 8
    for (int k = 0; k < CSZ; k++) m = f2max(m, base[k * rs2]);
    ((float2*)(g_cmax + ((size_t)b * NCH + q) * NH))[h2] = m;

    __syncthreads();
    int cnt = s_cnt;
    for (int j = 0; j < cnt; j++) {
        int n = s_n[j];
        int r = s_r[j];
        float2 ml = make_float2(-FLT_MAX, -FLT_MAX);
        float2 mr = ml;
#pragma unroll 4
        for (int k = 0; k < CSZ; k++) {   // L1-hot re-read of the block tile
            float2 v = base[k * rs2];
            if (k < r) ml = f2max(ml, v);
            else       mr = f2max(mr, v);
        }
        ((float2*)(g_plp + (size_t)n * NH))[h2] = ml;
        ((float2*)(g_prp + (size_t)n * NH))[h2] = mr;
    }
}

// ---------------------------------------------------------------------------
// Kernel B: prefix/suffix max over chunk maxes, emit pooled per candidate.
// ---------------------------------------------------------------------------
__global__ void k_scan_combine(const int* __restrict__ cb,
                               const int* __restrict__ cc) {
    __shared__ float sh_pref[NCH][256];
    __shared__ float sh_suf[NCH][256];
    __shared__ int s_cnt;
    __shared__ int s_n[NCAND];
    __shared__ int s_q[NCAND];

    int tid = threadIdx.x;
    int h = blockIdx.x * 256 + tid;
    int b = blockIdx.y;

    if (tid == 0) s_cnt = 0;
    __syncthreads();
    if (cb[tid] == b) {
        int p = atomicAdd(&s_cnt, 1);
        s_n[p] = tid;
        s_q[p] = cc[tid] >> 5;
    }

    const float* cm = g_cmax + (size_t)b * NCH * NH + h;
    float v[NCH];
#pragma unroll
    for (int q = 0; q < NCH; q++) v[q] = cm[(size_t)q * NH];

    float run = -FLT_MAX;
#pragma unroll
    for (int q = 0; q < NCH; q++) {
        sh_pref[q][tid] = run;
        run = fmaxf(run, v[q]);
    }
    run = -FLT_MAX;
#pragma unroll
    for (int q = NCH - 1; q >= 0; q--) {
        sh_suf[q][tid] = run;
        run = fmaxf(run, v[q]);
    }
    __syncthreads();

    int cnt = s_cnt;
    for (int j = 0; j < cnt; j++) {
        int n = s_n[j];
        int q = s_q[j];
        float pl = fmaxf(g_plp[(size_t)n * NH + h], sh_pref[q][tid]);
        float pr = fmaxf(g_prp[(size_t)n * NH + h], sh_suf[q][tid]);
        g_pooled[(size_t)n * (2 * NH) + h] = pl;
        g_pooled[(size_t)n * (2 * NH) + NH + h] = pr;
    }
}

// ---------------------------------------------------------------------------
// Kernel C: gemm with fused reduction. Block = (cand-oct, label-quad),
// 8 warps = K-splits of the SAME output tile; K-reduction completes in smem
// and writes out directly. Lane holds 8 A-float4 + 4 W-float4 per step.
// ---------------------------------------------------------------------------
__global__ __launch_bounds__(256) void k_gemm(const float* __restrict__ bias,
                                              float* __restrict__ out) {
    __shared__ float sp[SPLIT][32];
    int wid = threadIdx.x >> 5;     // K-split 0..7
    int lane = threadIdx.x & 31;
    int co = blockIdx.x;            // cand-oct 0..31
    int lq = blockIdx.y;            // label-quad 0..8
    int kbase = wid * KS;

    const float4* A = (const float4*)(g_pooled + (size_t)(co * 8) * (2 * NH) + kbase);
    const float4* Wt = (const float4*)(g_Wt + (size_t)(lq * 4) * (2 * NH) + kbase);
    const int rs = (2 * NH) / 4;

    float acc[8][4];
#pragma unroll
    for (int c = 0; c < 8; c++)
#pragma unroll
        for (int l = 0; l < 4; l++) acc[c][l] = 0.f;

#pragma unroll
    for (int step = 0; step < KS / 128; step++) {
        int i = lane + step * 32;
        float4 a[8], w[4];
#pragma unroll
        for (int c = 0; c < 8; c++) a[c] = A[c * rs + i];
#pragma unroll
        for (int l = 0; l < 4; l++) w[l] = Wt[l * rs + i];
#pragma unroll
        for (int c = 0; c < 8; c++)
#pragma unroll
            for (int l = 0; l < 4; l++) {
                acc[c][l] += a[c].x * w[l].x;
                acc[c][l] += a[c].y * w[l].y;
                acc[c][l] += a[c].z * w[l].z;
                acc[c][l] += a[c].w * w[l].w;
            }
    }

#pragma unroll
    for (int c = 0; c < 8; c++)
#pragma unroll
        for (int l = 0; l < 4; l++) {
            float s = acc[c][l];
#pragma unroll
            for (int o = 16; o; o >>= 1) s += __shfl_xor_sync(0xffffffffu, s, o);
            if (lane == 0) sp[wid][c * 4 + l] = s;
        }
    __syncthreads();

    if (threadIdx.x < 32) {
        int c = threadIdx.x >> 2;
        int l = threadIdx.x & 3;
        int label = lq * 4 + l;
        if (label < NL) {
            float s = bias[label];
#pragma unroll
            for (int w = 0; w < SPLIT; w++) s += sp[w][threadIdx.x];
            out[(size_t)(co * 8 + c) * NL + label] = s;
        }
    }
}

// ---------------------------------------------------------------------------
extern "C" void kernel_launch(void* const* d_in, const int* in_sizes, int n_in,
                              void* d_out, int out_size) {
    const float* hidden = (const float*)d_in[0];
    const float* W = (const float*)d_in[1];
    const float* bias = (const float*)d_in[2];
    const int* cb = (const int*)d_in[3];
    const int* cc = (const int*)d_in[4];
    float* out = (float*)d_out;

    k_A<<<CMB + WTB, 256>>>(hidden, W, cb, cc);

    dim3 gB(NH / 256, NB);
    k_scan_combine<<<gB, 256>>>(cb, cc);

    dim3 gC(32, 9);
    k_gemm<<<gC, 256>>>(bias, out);
}

// round 11
// speedup vs baseline: 1.0992x; 1.0992x over previous
#include <cuda_runtime.h>
#include <float.h>

#define NB 32
#define NS 512
#define NH 1024
#define NCAND 256
#define NL 34
#define NLP 36      // labels padded to 9 quads
#define NCH 16      // chunks per sequence
#define CSZ 32      // tokens per chunk
#define SPLIT 8     // K-split (warps per gemm block)
#define KS (2 * NH / SPLIT)   // 256 floats per split
#define CMB (NB * NCH * 2)    // 1024 chunk cells (2 h-halves of 512 floats)
#define WTB 288               // wt blocks (288*256 = 36*2048)

// Scratch (__device__ globals; no allocation allowed)
__device__ float g_cmax[NB * NCH * NH];
__device__ float g_plp[NCAND * NH];
__device__ float g_prp[NCAND * NH];
__device__ float g_pooled[NCAND * 2 * NH];
__device__ float g_Wt[NLP * 2 * NH];             // W transposed+padded [36][2048]

__device__ __forceinline__ float2 f2max(float2 a, float2 b) {
    float2 r;
    r.x = fmaxf(a.x, b.x);
    r.y = fmaxf(a.y, b.y);
    return r;
}

// ---------------------------------------------------------------------------
// Kernel A (fused): per-(b,q,h-half) chunk maxes. Thread owns 2 h via float2
// and keeps ALL 32 token values register-resident (v[32] float2 = 64 regs):
// no re-read for candidate partials (round-10's L1 re-read actually cost
// 32 MB of L2 traffic), and the full-unroll load batch maximizes in-flight
// bytes (~256 B/thread, ~196 KB/SM at 3 blocks/SM), which is what DRAM%
// tracked across rounds 8-10. W transpose rides along as trailing blocks.
// ---------------------------------------------------------------------------
__global__ __launch_bounds__(256, 3) void k_A(const float* __restrict__ hidden,
                                              const float* __restrict__ W,
                                              const int* __restrict__ cb,
                                              const int* __restrict__ cc) {
    int bid = blockIdx.x;
    int tid = threadIdx.x;

    if (bid >= CMB) {   // ---- W transpose part ----
        int idx = (bid - CMB) * 256 + tid;
        int l = idx >> 11;
        int k = idx & (2 * NH - 1);
        g_Wt[idx] = (l < NL) ? W[(size_t)k * NL + l] : 0.f;
        return;
    }

    // ---- chunk cell: bid = b*32 + q*2 + hb; thread owns 2 h ----
    __shared__ int s_cnt;
    __shared__ int s_n[NCAND];
    __shared__ int s_r[NCAND];

    int b = bid >> 5;
    int q = (bid >> 1) & 15;
    int hb = bid & 1;
    int h2 = hb * 256 + tid;        // float2 index within the 1024-float row

    if (tid == 0) s_cnt = 0;
    __syncthreads();
    {
        int cn = cc[tid];           // tid in [0,256) == NCAND
        if (cb[tid] == b && (cn >> 5) == q) {
            int p = atomicAdd(&s_cnt, 1);
            s_n[p] = tid;
            s_r[p] = cn & 31;
        }
    }

    const float2* base =
        (const float2*)(hidden + ((size_t)(b * NS + q * CSZ)) * NH) + h2;
    const int rs2 = NH / 2;         // token stride in float2

    float2 v[CSZ];
#pragma unroll
    for (int k = 0; k < CSZ; k++) v[k] = base[k * rs2];

    // Pairwise tree reduce (short dependency chains).
    float2 m = make_float2(-FLT_MAX, -FLT_MAX);
#pragma unroll
    for (int k = 0; k < CSZ; k += 4) {
        float2 t0 = f2max(v[k], v[k + 1]);
        float2 t1 = f2max(v[k + 2], v[k + 3]);
        m = f2max(m, f2max(t0, t1));
    }
    ((float2*)(g_cmax + ((size_t)b * NCH + q) * NH))[h2] = m;

    __syncthreads();
    int cnt = s_cnt;
    for (int j = 0; j < cnt; j++) {
        int n = s_n[j];
        int r = s_r[j];
        float2 ml = make_float2(-FLT_MAX, -FLT_MAX);
        float2 mr = ml;
#pragma unroll
        for (int k = 0; k < CSZ; k++) {
            if (k < r) ml = f2max(ml, v[k]);
            else       mr = f2max(mr, v[k]);
        }
        ((float2*)(g_plp + (size_t)n * NH))[h2] = ml;
        ((float2*)(g_prp + (size_t)n * NH))[h2] = mr;
    }
}

// ---------------------------------------------------------------------------
// Kernel B: prefix/suffix max over chunk maxes, emit pooled per candidate.
// ---------------------------------------------------------------------------
__global__ void k_scan_combine(const int* __restrict__ cb,
                               const int* __restrict__ cc) {
    __shared__ float sh_pref[NCH][256];
    __shared__ float sh_suf[NCH][256];
    __shared__ int s_cnt;
    __shared__ int s_n[NCAND];
    __shared__ int s_q[NCAND];

    int tid = threadIdx.x;
    int h = blockIdx.x * 256 + tid;
    int b = blockIdx.y;

    if (tid == 0) s_cnt = 0;
    __syncthreads();
    if (cb[tid] == b) {
        int p = atomicAdd(&s_cnt, 1);
        s_n[p] = tid;
        s_q[p] = cc[tid] >> 5;
    }

    const float* cm = g_cmax + (size_t)b * NCH * NH + h;
    float v[NCH];
#pragma unroll
    for (int q = 0; q < NCH; q++) v[q] = cm[(size_t)q * NH];

    float run = -FLT_MAX;
#pragma unroll
    for (int q = 0; q < NCH; q++) {
        sh_pref[q][tid] = run;
        run = fmaxf(run, v[q]);
    }
    run = -FLT_MAX;
#pragma unroll
    for (int q = NCH - 1; q >= 0; q--) {
        sh_suf[q][tid] = run;
        run = fmaxf(run, v[q]);
    }
    __syncthreads();

    int cnt = s_cnt;
    for (int j = 0; j < cnt; j++) {
        int n = s_n[j];
        int q = s_q[j];
        float pl = fmaxf(g_plp[(size_t)n * NH + h], sh_pref[q][tid]);
        float pr = fmaxf(g_prp[(size_t)n * NH + h], sh_suf[q][tid]);
        g_pooled[(size_t)n * (2 * NH) + h] = pl;
        g_pooled[(size_t)n * (2 * NH) + NH + h] = pr;
    }
}

// ---------------------------------------------------------------------------
// Kernel C: gemm with fused reduction. Block = (cand-oct, label-quad),
// 8 warps = K-splits of the SAME output tile; K-reduction completes in smem
// and writes out directly. Lane holds 8 A-float4 + 4 W-float4 per step.
// ---------------------------------------------------------------------------
__global__ __launch_bounds__(256) void k_gemm(const float* __restrict__ bias,
                                              float* __restrict__ out) {
    __shared__ float sp[SPLIT][32];
    int wid = threadIdx.x >> 5;     // K-split 0..7
    int lane = threadIdx.x & 31;
    int co = blockIdx.x;            // cand-oct 0..31
    int lq = blockIdx.y;            // label-quad 0..8
    int kbase = wid * KS;

    const float4* A = (const float4*)(g_pooled + (size_t)(co * 8) * (2 * NH) + kbase);
    const float4* Wt = (const float4*)(g_Wt + (size_t)(lq * 4) * (2 * NH) + kbase);
    const int rs = (2 * NH) / 4;

    float acc[8][4];
#pragma unroll
    for (int c = 0; c < 8; c++)
#pragma unroll
        for (int l = 0; l < 4; l++) acc[c][l] = 0.f;

#pragma unroll
    for (int step = 0; step < KS / 128; step++) {
        int i = lane + step * 32;
        float4 a[8], w[4];
#pragma unroll
        for (int c = 0; c < 8; c++) a[c] = A[c * rs + i];
#pragma unroll
        for (int l = 0; l < 4; l++) w[l] = Wt[l * rs + i];
#pragma unroll
        for (int c = 0; c < 8; c++)
#pragma unroll
            for (int l = 0; l < 4; l++) {
                acc[c][l] += a[c].x * w[l].x;
                acc[c][l] += a[c].y * w[l].y;
                acc[c][l] += a[c].z * w[l].z;
                acc[c][l] += a[c].w * w[l].w;
            }
    }

#pragma unroll
    for (int c = 0; c < 8; c++)
#pragma unroll
        for (int l = 0; l < 4; l++) {
            float s = acc[c][l];
#pragma unroll
            for (int o = 16; o; o >>= 1) s += __shfl_xor_sync(0xffffffffu, s, o);
            if (lane == 0) sp[wid][c * 4 + l] = s;
        }
    __syncthreads();

    if (threadIdx.x < 32) {
        int c = threadIdx.x >> 2;
        int l = threadIdx.x & 3;
        int label = lq * 4 + l;
        if (label < NL) {
            float s = bias[label];
#pragma unroll
            for (int w = 0; w < SPLIT; w++) s += sp[w][threadIdx.x];
            out[(size_t)(co * 8 + c) * NL + label] = s;
        }
    }
}

// ---------------------------------------------------------------------------
extern "C" void kernel_launch(void* const* d_in, const int* in_sizes, int n_in,
                              void* d_out, int out_size) {
    const float* hidden = (const float*)d_in[0];
    const float* W = (const float*)d_in[1];
    const float* bias = (const float*)d_in[2];
    const int* cb = (const int*)d_in[3];
    const int* cc = (const int*)d_in[4];
    float* out = (float*)d_out;

    k_A<<<CMB + WTB, 256>>>(hidden, W, cb, cc);

    dim3 gB(NH / 256, NB);
    k_scan_combine<<<gB, 256>>>(cb, cc);

    dim3 gC(32, 9);
    k_gemm<<<gC, 256>>>(bias, out);
}